// round 10
// baseline (speedup 1.0000x reference)
#include <cuda_runtime.h>
#include <stdint.h>

#define RMS_EPS 1e-6f

// 256-bit global load/store helpers (sm_100+ / Blackwell).
__device__ __forceinline__ void ldg256(const float* p, float v[8]) {
    asm volatile("ld.global.v8.f32 {%0,%1,%2,%3,%4,%5,%6,%7}, [%8];"
        : "=f"(v[0]), "=f"(v[1]), "=f"(v[2]), "=f"(v[3]),
          "=f"(v[4]), "=f"(v[5]), "=f"(v[6]), "=f"(v[7])
        : "l"(p));
}
__device__ __forceinline__ void stg256(float* p, const float v[8]) {
    asm volatile("st.global.v8.f32 [%0], {%1,%2,%3,%4,%5,%6,%7,%8};"
        :: "l"(p),
           "f"(v[0]), "f"(v[1]), "f"(v[2]), "f"(v[3]),
           "f"(v[4]), "f"(v[5]), "f"(v[6]), "f"(v[7])
        : "memory");
}

// 1024-thread CTA = two independent 512-thread row groups with decoupled
// named barriers. Per-group structure identical to the R9 champion:
// 16 warps, 8 elems/thread, 2x LDG.256 + 2x STG.256.
__global__ void __launch_bounds__(1024)
dequant_add_rmsnorm_quant_kernel(const int*   __restrict__ x,
                                 const float* __restrict__ residual,
                                 const float* __restrict__ scale,
                                 const float* __restrict__ weight,
                                 const float* __restrict__ dqs,
                                 float*       __restrict__ out_q,   // output 0 (quantized values as f32)
                                 float*       __restrict__ res_out, // output 1 (res_new as f32)
                                 int H)
{
    const int tid   = threadIdx.x;
    const int group = tid >> 9;          // 0 or 1: which row this half-CTA owns
    const int gtid  = tid & 511;         // thread id within the row group
    const int row   = (blockIdx.x << 1) | group;
    const size_t base = (size_t)row * (size_t)H;
    const int i0 = gtid << 3;            // 8 elements per thread (32B-aligned)
    const int gwid = gtid >> 5;          // warp id within group (0..15)
    const int lid  = tid & 31;
    const int barid = group + 1;         // named barrier 1 or 2, 512 threads each

    const float s = __ldg(scale + row) * __ldg(dqs);

    // ---- front-batched 256-bit loads ----
    float xf[8], rf[8];
    ldg256((const float*)(x + base + i0), xf);   // int32 bits in f32 regs
    ldg256(residual + base + i0, rf);

    float r[8];
    #pragma unroll
    for (int i = 0; i < 8; i++)
        r[i] = fmaf((float)__float_as_int(xf[i]), s, rf[i]);

    // res_new (output 1) while hot in registers
    stg256(res_out + base + i0, r);

    float ss = 0.f;
    #pragma unroll
    for (int i = 0; i < 8; i++) ss = fmaf(r[i], r[i], ss);

    // ---- per-group reduction: 16 warps, decoupled named barriers ----
    #pragma unroll
    for (int o = 16; o > 0; o >>= 1)
        ss += __shfl_xor_sync(0xFFFFFFFFu, ss, o);

    __shared__ float wsum[2][16];
    __shared__ float inv_s[2];
    if (lid == 0) wsum[group][gwid] = ss;
    asm volatile("bar.sync %0, 512;" :: "r"(barid) : "memory");

    if (gtid < 32) {
        float v = (lid < 16) ? wsum[group][lid] : 0.f;
        #pragma unroll
        for (int o = 8; o > 0; o >>= 1)
            v += __shfl_xor_sync(0xFFFFFFFFu, v, o);
        if (lid == 0) inv_s[group] = 1.0f / sqrtf(v / (float)H + RMS_EPS);
    }
    asm volatile("bar.sync %0, 512;" :: "r"(barid) : "memory");
    const float inv = inv_s[group];

    // ---- normalize, weight, round-half-even, saturate ----
    float w[8];
    ldg256(weight + i0, w);

    float q[8];
    #pragma unroll
    for (int i = 0; i < 8; i++) {
        float t = rintf(r[i] * inv * w[i]);      // jnp.round = half-to-even
        q[i] = fminf(fmaxf(t, -128.f), 127.f);   // clip; int8 value as f32
    }
    stg256(out_q + base + i0, q);
}

extern "C" void kernel_launch(void* const* d_in, const int* in_sizes, int n_in,
                              void* d_out, int out_size)
{
    const int*   x        = (const int*)  d_in[0];
    const float* residual = (const float*)d_in[1];
    const float* scale    = (const float*)d_in[2];
    const float* weight   = (const float*)d_in[3];
    const float* dqs      = (const float*)d_in[4];

    const int T  = in_sizes[2];   // scale is [T]
    const int H  = in_sizes[3];   // weight is [H]

    // Outputs cast to f32 and concatenated: [quant | res_new]
    float* out_q   = (float*)d_out;
    float* res_out = (float*)d_out + (size_t)out_size / 2;

    // Two rows per 1024-thread CTA
    dequant_add_rmsnorm_quant_kernel<<<T / 2, 1024>>>(
        x, residual, scale, weight, dqs, out_q, res_out, H);
}

// round 11
// speedup vs baseline: 1.0146x; 1.0146x over previous
#include <cuda_runtime.h>
#include <stdint.h>

#define RMS_EPS 1e-6f

// 256-bit global load/store helpers (sm_100+ / Blackwell).
__device__ __forceinline__ void ldg256(const float* p, float v[8]) {
    asm volatile("ld.global.v8.f32 {%0,%1,%2,%3,%4,%5,%6,%7}, [%8];"
        : "=f"(v[0]), "=f"(v[1]), "=f"(v[2]), "=f"(v[3]),
          "=f"(v[4]), "=f"(v[5]), "=f"(v[6]), "=f"(v[7])
        : "l"(p));
}
__device__ __forceinline__ void stg256(float* p, const float v[8]) {
    asm volatile("st.global.v8.f32 [%0], {%1,%2,%3,%4,%5,%6,%7,%8};"
        :: "l"(p),
           "f"(v[0]), "f"(v[1]), "f"(v[2]), "f"(v[3]),
           "f"(v[4]), "f"(v[5]), "f"(v[6]), "f"(v[7])
        : "memory");
}

// R9 champion (512 threads, 16 warps, 8 elems/thread, LDG/STG.256) with the
// weight load hoisted into the front batch (MLP_p1 = 5) so the post-barrier
// epilogue has no load dependency.
__global__ void __launch_bounds__(512)
dequant_add_rmsnorm_quant_kernel(const int*   __restrict__ x,
                                 const float* __restrict__ residual,
                                 const float* __restrict__ scale,
                                 const float* __restrict__ weight,
                                 const float* __restrict__ dqs,
                                 float*       __restrict__ out_q,   // output 0 (quantized values as f32)
                                 float*       __restrict__ res_out, // output 1 (res_new as f32)
                                 int H)
{
    const int row = blockIdx.x;
    const int tid = threadIdx.x;
    const size_t base = (size_t)row * (size_t)H;
    const int i0 = tid << 3;  // 8 elements per thread (32B-aligned offsets)

    const float s = __ldg(scale + row) * __ldg(dqs);

    // ---- front-batched 256-bit loads (3 LDG.256: x, residual, weight) ----
    float xf[8], rf[8], w[8];
    ldg256((const float*)(x + base + i0), xf);   // int32 bits in f32 regs
    ldg256(residual + base + i0, rf);
    ldg256(weight + i0, w);                      // L1/L2-resident after row 0

    float r[8];
    #pragma unroll
    for (int i = 0; i < 8; i++)
        r[i] = fmaf((float)__float_as_int(xf[i]), s, rf[i]);

    // res_new (output 1) while hot in registers — 256-bit store
    stg256(res_out + base + i0, r);

    float ss = 0.f;
    #pragma unroll
    for (int i = 0; i < 8; i++) ss = fmaf(r[i], r[i], ss);

    // ---- block reduction: 16 warps (proven structure) ----
    #pragma unroll
    for (int o = 16; o > 0; o >>= 1)
        ss += __shfl_xor_sync(0xFFFFFFFFu, ss, o);

    __shared__ float wsum[16];
    __shared__ float inv_s;
    const int wid = tid >> 5, lid = tid & 31;
    if (lid == 0) wsum[wid] = ss;
    __syncthreads();
    if (tid < 32) {
        float v = (tid < 16) ? wsum[tid] : 0.f;
        #pragma unroll
        for (int o = 8; o > 0; o >>= 1)
            v += __shfl_xor_sync(0xFFFFFFFFu, v, o);
        if (tid == 0) inv_s = 1.0f / sqrtf(v / (float)H + RMS_EPS);
    }
    __syncthreads();
    const float inv = inv_s;

    // ---- normalize, weight, round-half-even, saturate (no loads here) ----
    float q[8];
    #pragma unroll
    for (int i = 0; i < 8; i++) {
        float t = rintf(r[i] * inv * w[i]);      // jnp.round = half-to-even
        q[i] = fminf(fmaxf(t, -128.f), 127.f);   // clip; int8 value as f32
    }
    stg256(out_q + base + i0, q);
}

extern "C" void kernel_launch(void* const* d_in, const int* in_sizes, int n_in,
                              void* d_out, int out_size)
{
    const int*   x        = (const int*)  d_in[0];
    const float* residual = (const float*)d_in[1];
    const float* scale    = (const float*)d_in[2];
    const float* weight   = (const float*)d_in[3];
    const float* dqs      = (const float*)d_in[4];

    const int T  = in_sizes[2];   // scale is [T]
    const int H  = in_sizes[3];   // weight is [H]

    // Outputs cast to f32 and concatenated: [quant | res_new]
    float* out_q   = (float*)d_out;
    float* res_out = (float*)d_out + (size_t)out_size / 2;

    const int threads = H / 8;   // H=4096 -> 512
    dequant_add_rmsnorm_quant_kernel<<<T, threads>>>(
        x, residual, scale, weight, dqs, out_q, res_out, H);
}

// round 12
// speedup vs baseline: 1.0231x; 1.0084x over previous
#include <cuda_runtime.h>
#include <stdint.h>

#define RMS_EPS 1e-6f

// 256-bit global load/store helpers (sm_100+ / Blackwell).
__device__ __forceinline__ void ldg256(const float* p, float v[8]) {
    asm volatile("ld.global.v8.f32 {%0,%1,%2,%3,%4,%5,%6,%7}, [%8];"
        : "=f"(v[0]), "=f"(v[1]), "=f"(v[2]), "=f"(v[3]),
          "=f"(v[4]), "=f"(v[5]), "=f"(v[6]), "=f"(v[7])
        : "l"(p));
}
__device__ __forceinline__ void stg256(float* p, const float v[8]) {
    asm volatile("st.global.v8.f32 [%0], {%1,%2,%3,%4,%5,%6,%7,%8};"
        :: "l"(p),
           "f"(v[0]), "f"(v[1]), "f"(v[2]), "f"(v[3]),
           "f"(v[4]), "f"(v[5]), "f"(v[6]), "f"(v[7])
        : "memory");
}

// R9/R11 champion structure (512 threads, 16 warps, 8 elems/thread,
// LDG/STG.256, weight hoisted) with BOTH stores grouped after the barrier:
// per-CTA traffic becomes [pure read burst] -> reduce -> [pure write burst],
// maximizing same-direction run length at the HBM controllers.
__global__ void __launch_bounds__(512)
dequant_add_rmsnorm_quant_kernel(const int*   __restrict__ x,
                                 const float* __restrict__ residual,
                                 const float* __restrict__ scale,
                                 const float* __restrict__ weight,
                                 const float* __restrict__ dqs,
                                 float*       __restrict__ out_q,   // output 0 (quantized values as f32)
                                 float*       __restrict__ res_out, // output 1 (res_new as f32)
                                 int H)
{
    const int row = blockIdx.x;
    const int tid = threadIdx.x;
    const size_t base = (size_t)row * (size_t)H;
    const int i0 = tid << 3;  // 8 elements per thread (32B-aligned offsets)

    const float s = __ldg(scale + row) * __ldg(dqs);

    // ---- front-batched 256-bit loads (x, residual, weight) ----
    float xf[8], rf[8], w[8];
    ldg256((const float*)(x + base + i0), xf);   // int32 bits in f32 regs
    ldg256(residual + base + i0, rf);
    ldg256(weight + i0, w);                      // L1/L2-resident after row 0

    float r[8];
    #pragma unroll
    for (int i = 0; i < 8; i++)
        r[i] = fmaf((float)__float_as_int(xf[i]), s, rf[i]);

    float ss = 0.f;
    #pragma unroll
    for (int i = 0; i < 8; i++) ss = fmaf(r[i], r[i], ss);

    // ---- block reduction: 16 warps (proven structure) ----
    #pragma unroll
    for (int o = 16; o > 0; o >>= 1)
        ss += __shfl_xor_sync(0xFFFFFFFFu, ss, o);

    __shared__ float wsum[16];
    __shared__ float inv_s;
    const int wid = tid >> 5, lid = tid & 31;
    if (lid == 0) wsum[wid] = ss;
    __syncthreads();
    if (tid < 32) {
        float v = (tid < 16) ? wsum[tid] : 0.f;
        #pragma unroll
        for (int o = 8; o > 0; o >>= 1)
            v += __shfl_xor_sync(0xFFFFFFFFu, v, o);
        if (tid == 0) inv_s = 1.0f / sqrtf(v / (float)H + RMS_EPS);
    }
    __syncthreads();
    const float inv = inv_s;

    // ---- epilogue: quantize, then both 256-bit stores back-to-back ----
    float q[8];
    #pragma unroll
    for (int i = 0; i < 8; i++) {
        float t = rintf(r[i] * inv * w[i]);      // jnp.round = half-to-even
        q[i] = fminf(fmaxf(t, -128.f), 127.f);   // clip; int8 value as f32
    }
    stg256(res_out + base + i0, r);   // res_new (output 1)
    stg256(out_q   + base + i0, q);   // quantized (output 0)
}

extern "C" void kernel_launch(void* const* d_in, const int* in_sizes, int n_in,
                              void* d_out, int out_size)
{
    const int*   x        = (const int*)  d_in[0];
    const float* residual = (const float*)d_in[1];
    const float* scale    = (const float*)d_in[2];
    const float* weight   = (const float*)d_in[3];
    const float* dqs      = (const float*)d_in[4];

    const int T  = in_sizes[2];   // scale is [T]
    const int H  = in_sizes[3];   // weight is [H]

    // Outputs cast to f32 and concatenated: [quant | res_new]
    float* out_q   = (float*)d_out;
    float* res_out = (float*)d_out + (size_t)out_size / 2;

    const int threads = H / 8;   // H=4096 -> 512
    dequant_add_rmsnorm_quant_kernel<<<T, threads>>>(
        x, residual, scale, weight, dqs, out_q, res_out, H);
}